// round 16
// baseline (speedup 1.0000x reference)
#include <cuda_runtime.h>
#include <cuda_fp16.h>
#include <math.h>
#include <stdint.h>

#define B_  2
#define T_  1024
#define D_  2048
#define H_  16
#define KVH_ 4
#define DH_ 128
#define REP_ 4

#define LAMBDA_INIT_F   0.35550906759096927f
#define ONE_MINUS_LI_F  0.64449093240903073f
#define GN_EPS_F        1e-5f
#define SCALE_F         0.08838834764831845f  // 1/sqrt(128)
#define ROPE_C          (-13.287712379549449f / 64.0f)   // -log2(10000)/64

// fp16 GEMM pipeline: BK=32 (two k16 slabs), 4 stages, row stride 40 halves
#define BKH  32
#define LDH  40
#define GEMM_SMEM_BYTES (4 * 128 * LDH * 2 * 2)   // 81920 B

// ---------------- scratch ----------------------------------------------------
static __device__ __half g_Qh[(size_t)B_*T_*H_*2*DH_];   // fp16 roped+scaled
static __device__ __half g_Kh[(size_t)B_*T_*KVH_*2*DH_];
static __device__ __half g_Vh[(size_t)B_*T_*KVH_*2*DH_];
static __device__ __half g_Xh[(size_t)B_*T_*D_];
static __device__ __half g_Wqh[(size_t)2*H_*DH_*D_];
static __device__ __half g_Wkh[(size_t)2*KVH_*DH_*D_];
static __device__ __half g_Wvh[(size_t)2*KVH_*DH_*D_];
static __device__ __half g_Woh[(size_t)D_*2*H_*DH_];
static __device__ __half g_Oh[(size_t)B_*T_*H_*2*DH_];
static __device__ float2 g_rope[(size_t)T_ * 64];        // (cos, sin) per (t, pair)
static __device__ float  g_lambda;

// ---------------- helpers ----------------------------------------------------
__device__ __forceinline__ void mma_f16(float* c, const uint32_t* a, const uint32_t* b) {
    asm volatile(
        "mma.sync.aligned.m16n8k16.row.col.f32.f16.f16.f32 "
        "{%0,%1,%2,%3}, {%4,%5,%6,%7}, {%8,%9}, {%0,%1,%2,%3};"
        : "+f"(c[0]), "+f"(c[1]), "+f"(c[2]), "+f"(c[3])
        : "r"(a[0]), "r"(a[1]), "r"(a[2]), "r"(a[3]), "r"(b[0]), "r"(b[1]));
}
__device__ __forceinline__ void ldsm4(uint32_t* r, uint32_t a) {
    asm volatile("ldmatrix.sync.aligned.m8n8.x4.shared.b16 {%0,%1,%2,%3}, [%4];"
        : "=r"(r[0]), "=r"(r[1]), "=r"(r[2]), "=r"(r[3]) : "r"(a));
}
__device__ __forceinline__ void ldsm4t(uint32_t* r, uint32_t a) {
    asm volatile("ldmatrix.sync.aligned.m8n8.x4.trans.shared.b16 {%0,%1,%2,%3}, [%4];"
        : "=r"(r[0]), "=r"(r[1]), "=r"(r[2]), "=r"(r[3]) : "r"(a));
}
__device__ __forceinline__ void cp_async16(uint32_t smem_dst, const void* gsrc) {
    asm volatile("cp.async.cg.shared.global [%0], [%1], 16;" :: "r"(smem_dst), "l"(gsrc));
}
__device__ __forceinline__ void cp_commit() {
    asm volatile("cp.async.commit_group;" ::: "memory");
}
template <int N>
__device__ __forceinline__ void cp_wait() {
    asm volatile("cp.async.wait_group %0;" :: "n"(N) : "memory");
}
__device__ __forceinline__ uint32_t h2_bits(float a, float b) {
    __half2 t = __floats2half2_rn(a, b);
    return *(uint32_t*)&t;
}

// ---------------- fused fp32 -> fp16 convert for 5 tensors --------------------
#define S0_ 1048576
#define S1_ 2097152
#define S2_ 524288
#define S3_ 524288
#define S4_ 2097152
__global__ void f2h5_kernel(const float* __restrict__ x,  const float* __restrict__ Wq,
                            const float* __restrict__ Wk, const float* __restrict__ Wv,
                            const float* __restrict__ Wo,
                            __half* __restrict__ xh,  __half* __restrict__ Wqh,
                            __half* __restrict__ Wkh, __half* __restrict__ Wvh,
                            __half* __restrict__ Woh) {
    int i = blockIdx.x * blockDim.x + threadIdx.x;
    const float* s; __half* d; int off;
    if (i < S0_)                       { s = x;  d = xh;  off = i; }
    else if (i < S0_ + S1_)            { s = Wq; d = Wqh; off = i - S0_; }
    else if (i < S0_ + S1_ + S2_)      { s = Wk; d = Wkh; off = i - S0_ - S1_; }
    else if (i < S0_ + S1_ + S2_ + S3_){ s = Wv; d = Wvh; off = i - S0_ - S1_ - S2_; }
    else                               { s = Wo; d = Woh; off = i - S0_ - S1_ - S2_ - S3_; }
    float4 v = ((const float4*)s)[off];
    ((__half2*)d)[2 * off]     = __floats2half2_rn(v.x, v.y);
    ((__half2*)d)[2 * off + 1] = __floats2half2_rn(v.z, v.w);
}

// ---------------- prep: lambda scalar + RoPE cos/sin table --------------------
__global__ void prep_kernel(const float* __restrict__ lq1, const float* __restrict__ lk1,
                            const float* __restrict__ lq2, const float* __restrict__ lk2,
                            const int* __restrict__ pos) {
    int gid = blockIdx.x * blockDim.x + threadIdx.x;
    // rope table: 1024 t x 64 pairs
    if (gid < T_ * 64) {
        int i = gid & 63;
        int t = gid >> 6;
        float inv = exp2f((float)i * ROPE_C);
        float ang = (float)pos[t] * inv;
        float s, c;
        sincosf(ang, &s, &c);
        g_rope[gid] = make_float2(c, s);
    }
    // lambda (block 0, warp 0)
    if (blockIdx.x == 0 && threadIdx.x < 32) {
        int lane = threadIdx.x;
        float d1 = 0.f, d2 = 0.f;
        #pragma unroll
        for (int i = 0; i < 4; i++) {
            int idx = lane * 4 + i;
            d1 += lq1[idx] * lk1[idx];
            d2 += lq2[idx] * lk2[idx];
        }
        #pragma unroll
        for (int o = 16; o; o >>= 1) {
            d1 += __shfl_xor_sync(0xffffffffu, d1, o);
            d2 += __shfl_xor_sync(0xffffffffu, d2, o);
        }
        if (lane == 0)
            g_lambda = expf(d1) - expf(d2) + LAMBDA_INIT_F;
    }
}

// ---------------- fp16 m16n8k16 GEMM body (BK=32, ldmatrix, 4-stage cp.async) -
// MODE: 0 = fp32 out, 1 = fp16 out, 2 = fp16 out with table RoPE (+scale)
template <int MODE>
__device__ __forceinline__ void gemm_body_h(
    const __half* __restrict__ Ablk, const __half* __restrict__ Bblk,
    void* __restrict__ Cblk, int K, int ldc, __half* smem,
    int rowbase, int colbase, float scale)
{
    const int tid  = threadIdx.x;
    const int warp = tid >> 5;
    const int lane = tid & 31;
    const int wm = (warp >> 2) * 64;
    const int wn = (warp & 3) * 32;
    const int lr = lane >> 2;
    const int lc = lane & 3;

    const uint32_t smb = (uint32_t)__cvta_generic_to_shared(smem);
    const uint32_t bofs = 4u * 128u * LDH * 2;   // B region offset (bytes)

    const int l_row0 = tid >> 2;           // 0..63
    const int l_row1 = l_row0 + 64;        // 64..127
    const int l_c0   = (tid & 3) * 8;      // 0,8,16,24 halves
    const __half* Ag0 = Ablk + (size_t)l_row0 * K + l_c0;
    const __half* Ag1 = Ablk + (size_t)l_row1 * K + l_c0;
    const __half* Bg0 = Bblk + (size_t)l_row0 * K + l_c0;
    const __half* Bg1 = Bblk + (size_t)l_row1 * K + l_c0;

    uint32_t a_dst0[4], a_dst1[4];
    #pragma unroll
    for (int s = 0; s < 4; s++) {
        a_dst0[s] = smb + (s * 128 * LDH + l_row0 * LDH + l_c0) * 2;
        a_dst1[s] = smb + (s * 128 * LDH + l_row1 * LDH + l_c0) * 2;
    }

    const int a_lr  = lane & 15;
    const int a_c8  = (lane >> 4) * 8;
    const int b_row = (lane & 7) + ((lane >> 4) << 3);
    const int b_k8  = ((lane >> 3) & 1) * 8;

    uint32_t a_lm[4], b_lm[4];
    #pragma unroll
    for (int s = 0; s < 4; s++) {
        a_lm[s] = smb + (s * 128 * LDH + (wm + a_lr) * LDH + a_c8) * 2;
        b_lm[s] = smb + bofs + (s * 128 * LDH + (wn + b_row) * LDH + b_k8) * 2;
    }

    float acc[4][4][4];
    #pragma unroll
    for (int mi = 0; mi < 4; mi++)
        #pragma unroll
        for (int ni = 0; ni < 4; ni++)
            #pragma unroll
            for (int r = 0; r < 4; r++)
                acc[mi][ni][r] = 0.f;

    const int nt = K / BKH;

    #pragma unroll
    for (int p = 0; p < 3; p++) {
        const size_t k0 = (size_t)p * BKH;
        cp_async16(a_dst0[p],        Ag0 + k0);
        cp_async16(a_dst1[p],        Ag1 + k0);
        cp_async16(a_dst0[p] + bofs, Bg0 + k0);
        cp_async16(a_dst1[p] + bofs, Bg1 + k0);
        cp_commit();
    }

    for (int t = 0; t < nt; t++) {
        cp_wait<2>();
        __syncthreads();
        const int s = t & 3;

        #pragma unroll
        for (int kk = 0; kk < 2; kk++) {
            uint32_t af[4][4], bf[4][2];
            #pragma unroll
            for (int mi = 0; mi < 4; mi++)
                ldsm4(af[mi], a_lm[s] + kk * 32 + mi * (16 * LDH * 2));
            {
                uint32_t bt[4];
                ldsm4(bt, b_lm[s] + kk * 32);
                bf[0][0] = bt[0]; bf[0][1] = bt[1]; bf[1][0] = bt[2]; bf[1][1] = bt[3];
                ldsm4(bt, b_lm[s] + kk * 32 + 16 * LDH * 2);
                bf[2][0] = bt[0]; bf[2][1] = bt[1]; bf[3][0] = bt[2]; bf[3][1] = bt[3];
            }
            #pragma unroll
            for (int mi = 0; mi < 4; mi++)
                #pragma unroll
                for (int ni = 0; ni < 4; ni++)
                    mma_f16(acc[mi][ni], af[mi], bf[ni]);
        }

        if (t + 3 < nt) {
            const int sn = (t + 3) & 3;
            const size_t k0 = (size_t)(t + 3) * BKH;
            cp_async16(a_dst0[sn],        Ag0 + k0);
            cp_async16(a_dst1[sn],        Ag1 + k0);
            cp_async16(a_dst0[sn] + bofs, Bg0 + k0);
            cp_async16(a_dst1[sn] + bofs, Bg1 + k0);
        }
        cp_commit();
    }

    #pragma unroll
    for (int mi = 0; mi < 4; mi++) {
        #pragma unroll
        for (int ni = 0; ni < 4; ni++) {
            int r0 = wm + mi * 16 + lr;
            int cc = wn + ni * 8 + 2 * lc;
            if (MODE == 2) {
                __half* Ch = (__half*)Cblk;
                int ip = ((colbase + cc) & 127) >> 1;
                int t0 = (rowbase + r0) & (T_ - 1);
                int t1 = (rowbase + r0 + 8) & (T_ - 1);
                float2 cs0 = g_rope[t0 * 64 + ip];
                float2 cs1 = g_rope[t1 * 64 + ip];
                float e0 = (acc[mi][ni][0] * cs0.x - acc[mi][ni][1] * cs0.y) * scale;
                float o0 = (acc[mi][ni][0] * cs0.y + acc[mi][ni][1] * cs0.x) * scale;
                float e1 = (acc[mi][ni][2] * cs1.x - acc[mi][ni][3] * cs1.y) * scale;
                float o1 = (acc[mi][ni][2] * cs1.y + acc[mi][ni][3] * cs1.x) * scale;
                *(__half2*)&Ch[(size_t)r0 * ldc + cc]       = __floats2half2_rn(e0, o0);
                *(__half2*)&Ch[(size_t)(r0 + 8) * ldc + cc] = __floats2half2_rn(e1, o1);
            } else if (MODE == 1) {
                __half* Ch = (__half*)Cblk;
                *(__half2*)&Ch[(size_t)r0 * ldc + cc] =
                    __floats2half2_rn(acc[mi][ni][0], acc[mi][ni][1]);
                *(__half2*)&Ch[(size_t)(r0 + 8) * ldc + cc] =
                    __floats2half2_rn(acc[mi][ni][2], acc[mi][ni][3]);
            } else {
                float* Cf = (float*)Cblk;
                *(float2*)&Cf[(size_t)r0 * ldc + cc] =
                    make_float2(acc[mi][ni][0], acc[mi][ni][1]);
                *(float2*)&Cf[(size_t)(r0 + 8) * ldc + cc] =
                    make_float2(acc[mi][ni][2], acc[mi][ni][3]);
            }
        }
    }
}

// ---------------- fused QKV projection with RoPE epilogue ----------------------
__global__ void __launch_bounds__(256, 2) gemm_qkv_h(const __half* __restrict__ x,
                                                     const __half* __restrict__ Wq,
                                                     const __half* __restrict__ Wk,
                                                     const __half* __restrict__ Wv,
                                                     __half* __restrict__ Qh,
                                                     __half* __restrict__ Kh,
                                                     __half* __restrict__ Vh) {
    extern __shared__ __half hsmem[];
    const int bx = blockIdx.x;
    const int bm = blockIdx.y * 128;
    if (bx < 32) {
        int bn = bx * 128;
        gemm_body_h<2>(x + (size_t)bm * D_, Wq + (size_t)bn * D_,
                       Qh + (size_t)bm * 4096 + bn, D_, 4096, hsmem,
                       bm, bn, SCALE_F);
    } else if (bx < 40) {
        int bn = (bx - 32) * 128;
        gemm_body_h<2>(x + (size_t)bm * D_, Wk + (size_t)bn * D_,
                       Kh + (size_t)bm * 1024 + bn, D_, 1024, hsmem,
                       bm, bn, 1.0f);
    } else {
        int bn = (bx - 40) * 128;
        gemm_body_h<1>(x + (size_t)bm * D_, Wv + (size_t)bn * D_,
                       Vh + (size_t)bm * 1024 + bn, D_, 1024, hsmem,
                       0, 0, 1.0f);
    }
}

// ---------------- output projection --------------------------------------------
__global__ void __launch_bounds__(256, 2) gemm_out_h(const __half* __restrict__ A,
                                                     const __half* __restrict__ W,
                                                     float* __restrict__ C,
                                                     int N, int K) {
    extern __shared__ __half hsmem[];
    const int bm = blockIdx.y * 128;
    const int bn = blockIdx.x * 128;
    gemm_body_h<0>(A + (size_t)bm * K, W + (size_t)bn * K,
                   C + (size_t)bm * N + bn, K, N, hsmem,
                   0, 0, 1.0f);
}

// ---------------- fp16 dual flash attention + GroupNorm (R15 config) ----------
#define SMH_STAGE 34304
#define SMH_K2O   8704
#define SMH_VO    17408
#define SMH_QS    68608
#define SMH_TOT   85504      // halves -> 171008 B

__global__ void __launch_bounds__(512, 1) attn_kernel(const __half* __restrict__ Qh,
                                                      const __half* __restrict__ Kh,
                                                      const __half* __restrict__ Vh,
                                                      __half* __restrict__ Oh,
                                                      const float* __restrict__ gnw,
                                                      const float* __restrict__ gnb) {
    extern __shared__ __half hs[];
    __half (*QS)[264]  = (__half(*)[264])(hs + SMH_QS);
    float  (*Osm)[264] = (float(*)[264])hs;

    const int tid  = threadIdx.x;
    const int warp = tid >> 5;
    const int lane = tid & 31;
    const int lr = lane >> 2;
    const int lc = lane & 3;
    const int br = warp >> 3;
    const int rg = (warp >> 1) & 3;
    const int vh = warp & 1;

    const int bh = blockIdx.y;
    const int b = bh / H_;
    const int h = bh % H_;
    const int kvh = h / REP_;
    const int q0 = (gridDim.x - 1 - blockIdx.x) * 64;

    const uint32_t hsb = (uint32_t)__cvta_generic_to_shared(hs);

    const int lm_r = (lane & 7) + ((lane >> 3) & 1) * 8;
    const int lm_c8 = (lane >> 4) * 8;

    const uint32_t q_addr0 = hsb + (SMH_QS + (rg * 16 + lm_r) * 264 + br * 128 + lm_c8) * 2;
    const int k_key = (lane >> 4) * 8 + (lane & 7);
    const int k_dim = ((lane >> 3) & 1) * 8;
    const uint32_t k_base = hsb + ((br ? SMH_K2O : 0) + k_key * 136 + k_dim) * 2;
    const int v_key = ((lane >> 3) & 1) * 8 + (lane & 7);
    const uint32_t v_base = hsb + (SMH_VO + v_key * 264 + vh * 128 + (lane >> 4) * 8) * 2;

    #pragma unroll
    for (int r = 0; r < 4; r++) {
        int idx = tid + 512 * r;
        int qr = idx >> 5;
        int c8 = (idx & 31) * 8;
        uint4 v = *(const uint4*)&Qh[((size_t)(b * T_ + q0 + qr) * H_ + h) * 256 + c8];
        *(uint4*)&QS[qr][c8] = v;
    }

    float oacc[16][4];
    #pragma unroll
    for (int n = 0; n < 16; n++)
        #pragma unroll
        for (int r = 0; r < 4; r++)
            oacc[n][r] = 0.f;
    float m0 = -1e30f, m1 = -1e30f, l0 = 0.f, l1 = 0.f;

    const int row0 = q0 + rg * 16 + lr;
    const int row1 = row0 + 8;
    const int ntiles = q0 / 64 + 1;

    auto issue_tile = [&](int kt, int st) {
        const int k0 = kt * 64;
        const uint32_t sb = hsb + st * (SMH_STAGE * 2);
        #pragma unroll
        for (int r = 0; r < 4; r++) {
            int idx = tid + 512 * r;
            int key = idx >> 5;
            int c8 = idx & 31;
            size_t kb = ((size_t)(b * T_ + k0 + key) * KVH_ + kvh) * 256;
            uint32_t kd;
            if (c8 < 16) kd = sb + (key * 136 + c8 * 8) * 2;
            else         kd = sb + (SMH_K2O + key * 136 + (c8 - 16) * 8) * 2;
            cp_async16(kd, &Kh[kb + c8 * 8]);
            cp_async16(sb + (SMH_VO + key * 264 + c8 * 8) * 2, &Vh[kb + c8 * 8]);
        }
    };

    issue_tile(0, 0);
    cp_commit();

    for (int kt = 0; kt < ntiles; kt++) {
        const int st = kt & 1;

        cp_wait<0>();
        __syncthreads();
        if (kt + 1 < ntiles) {
            issue_tile(kt + 1, st ^ 1);
            cp_commit();
        }

        const uint32_t soff = st * (SMH_STAGE * 2);
        const bool lasttile = (kt == ntiles - 1);

        #pragma unroll
        for (int hk = 0; hk < 2; hk++) {
            const int k0 = kt * 64 + hk * 32;
            const uint32_t k_addr0 = k_base + soff + hk * (32 * 136 * 2);
            const uint32_t v_addr0 = v_base + soff + hk * (32 * 264 * 2);

            float sf[4][4];
            #pragma unroll
            for (int n = 0; n < 4; n++)
                #pragma unroll
                for (int r = 0; r < 4; r++)
                    sf[n][r] = 0.f;
            #pragma unroll
            for (int ks = 0; ks < 8; ks++) {
                uint32_t qa[4], kb0[4], kb1[4];
                ldsm4(qa, q_addr0 + ks * 32);
                ldsm4(kb0, k_addr0 + ks * 32);
                ldsm4(kb1, k_addr0 + ks * 32 + 16 * 136 * 2);
                mma_f16(sf[0], qa, kb0);
                mma_f16(sf[1], qa, kb0 + 2);
                mma_f16(sf[2], qa, kb1);
                mma_f16(sf[3], qa, kb1 + 2);
            }

            if (lasttile) {
                #pragma unroll
                for (int n = 0; n < 4; n++) {
                    int key = k0 + n * 8 + 2 * lc;
                    if (key     > row0) sf[n][0] = -1e30f;
                    if (key + 1 > row0) sf[n][1] = -1e30f;
                    if (key     > row1) sf[n][2] = -1e30f;
                    if (key + 1 > row1) sf[n][3] = -1e30f;
                }
            }

            float mx0 = -1e30f, mx1 = -1e30f;
            #pragma unroll
            for (int n = 0; n < 4; n++) {
                mx0 = fmaxf(mx0, fmaxf(sf[n][0], sf[n][1]));
                mx1 = fmaxf(mx1, fmaxf(sf[n][2], sf[n][3]));
            }
            mx0 = fmaxf(mx0, __shfl_xor_sync(0xffffffffu, mx0, 1));
            mx0 = fmaxf(mx0, __shfl_xor_sync(0xffffffffu, mx0, 2));
            mx1 = fmaxf(mx1, __shfl_xor_sync(0xffffffffu, mx1, 1));
            mx1 = fmaxf(mx1, __shfl_xor_sync(0xffffffffu, mx1, 2));

            float mn0 = fmaxf(m0, mx0), mn1 = fmaxf(m1, mx1);
            float c0 = __expf(m0 - mn0), c1 = __expf(m1 - mn1);
            m0 = mn0; m1 = mn1;

            float rs0 = 0.f, rs1 = 0.f;
            #pragma unroll
            for (int n = 0; n < 4; n++) {
                sf[n][0] = __expf(sf[n][0] - mn0);
                sf[n][1] = __expf(sf[n][1] - mn0);
                sf[n][2] = __expf(sf[n][2] - mn1);
                sf[n][3] = __expf(sf[n][3] - mn1);
                rs0 += sf[n][0] + sf[n][1];
                rs1 += sf[n][2] + sf[n][3];
            }
            rs0 += __shfl_xor_sync(0xffffffffu, rs0, 1);
            rs0 += __shfl_xor_sync(0xffffffffu, rs0, 2);
            rs1 += __shfl_xor_sync(0xffffffffu, rs1, 1);
            rs1 += __shfl_xor_sync(0xffffffffu, rs1, 2);
            l0 = l0 * c0 + rs0;
            l1 = l1 * c1 + rs1;

            #pragma unroll
            for (int n = 0; n < 16; n++) {
                oacc[n][0] *= c0; oacc[n][1] *= c0;
                oacc[n][2] *= c1; oacc[n][3] *= c1;
            }

            #pragma unroll
            for (int ks = 0; ks < 2; ks++) {
                uint32_t pa[4];
                pa[0] = h2_bits(sf[2*ks][0],   sf[2*ks][1]);
                pa[1] = h2_bits(sf[2*ks][2],   sf[2*ks][3]);
                pa[2] = h2_bits(sf[2*ks+1][0], sf[2*ks+1][1]);
                pa[3] = h2_bits(sf[2*ks+1][2], sf[2*ks+1][3]);
                #pragma unroll
                for (int np = 0; np < 8; np++) {
                    uint32_t vb4[4];
                    ldsm4t(vb4, v_addr0 + ks * (16 * 264 * 2) + np * 32);
                    mma_f16(oacc[np * 2],     pa, vb4);
                    mma_f16(oacc[np * 2 + 1], pa, vb4 + 2);
                }
            }
        }
    }

    __syncthreads();
    const int orow0 = rg * 16 + lr;
    const int vb = vh * 128;
    if (br == 0) {
        float r0 = 1.f / l0, r1 = 1.f / l1;
        #pragma unroll
        for (int n = 0; n < 16; n++) {
            *(float2*)&Osm[orow0]    [vb + n * 8 + 2 * lc] =
                make_float2(oacc[n][0] * r0, oacc[n][1] * r0);
            *(float2*)&Osm[orow0 + 8][vb + n * 8 + 2 * lc] =
                make_float2(oacc[n][2] * r1, oacc[n][3] * r1);
        }
    }
    __syncthreads();
    if (br == 1) {
        const float lam = g_lambda;
        float r0 = lam / l0, r1 = lam / l1;
        #pragma unroll
        for (int n = 0; n < 16; n++) {
            float2 a0 = *(float2*)&Osm[orow0]    [vb + n * 8 + 2 * lc];
            float2 a1 = *(float2*)&Osm[orow0 + 8][vb + n * 8 + 2 * lc];
            a0.x -= oacc[n][0] * r0; a0.y -= oacc[n][1] * r0;
            a1.x -= oacc[n][2] * r1; a1.y -= oacc[n][3] * r1;
            *(float2*)&Osm[orow0]    [vb + n * 8 + 2 * lc] = a0;
            *(float2*)&Osm[orow0 + 8][vb + n * 8 + 2 * lc] = a1;
        }
    }
    __syncthreads();

    const float4 gw0 = *(const float4*)&gnw[h * 256 + lane * 4];
    const float4 gw1 = *(const float4*)&gnw[h * 256 + 128 + lane * 4];
    const float4 gb0 = *(const float4*)&gnb[h * 256 + lane * 4];
    const float4 gb1 = *(const float4*)&gnb[h * 256 + 128 + lane * 4];
    #pragma unroll
    for (int i = 0; i < 4; i++) {
        int r = warp * 4 + i;
        float4 v0 = *(float4*)&Osm[r][lane * 4];
        float4 v1 = *(float4*)&Osm[r][128 + lane * 4];
        float sum = v0.x + v0.y + v0.z + v0.w + v1.x + v1.y + v1.z + v1.w;
        float ss  = v0.x*v0.x + v0.y*v0.y + v0.z*v0.z + v0.w*v0.w
                  + v1.x*v1.x + v1.y*v1.y + v1.z*v1.z + v1.w*v1.w;
        #pragma unroll
        for (int o = 16; o; o >>= 1) {
            sum += __shfl_xor_sync(0xffffffffu, sum, o);
            ss  += __shfl_xor_sync(0xffffffffu, ss, o);
        }
        float mean = sum * (1.f / 256.f);
        float var = ss * (1.f / 256.f) - mean * mean;
        float rstd = rsqrtf(var + GN_EPS_F);
        float o0x = ((v0.x - mean) * rstd * gw0.x + gb0.x) * ONE_MINUS_LI_F;
        float o0y = ((v0.y - mean) * rstd * gw0.y + gb0.y) * ONE_MINUS_LI_F;
        float o0z = ((v0.z - mean) * rstd * gw0.z + gb0.z) * ONE_MINUS_LI_F;
        float o0w = ((v0.w - mean) * rstd * gw0.w + gb0.w) * ONE_MINUS_LI_F;
        float o1x = ((v1.x - mean) * rstd * gw1.x + gb1.x) * ONE_MINUS_LI_F;
        float o1y = ((v1.y - mean) * rstd * gw1.y + gb1.y) * ONE_MINUS_LI_F;
        float o1z = ((v1.z - mean) * rstd * gw1.z + gb1.z) * ONE_MINUS_LI_F;
        float o1w = ((v1.w - mean) * rstd * gw1.w + gb1.w) * ONE_MINUS_LI_F;
        size_t ob = (size_t)(b * T_ + q0 + r) * 4096 + h * 256;
        *(__half2*)&Oh[ob + lane * 4]           = __floats2half2_rn(o0x, o0y);
        *(__half2*)&Oh[ob + lane * 4 + 2]       = __floats2half2_rn(o0z, o0w);
        *(__half2*)&Oh[ob + 128 + lane * 4]     = __floats2half2_rn(o1x, o1y);
        *(__half2*)&Oh[ob + 128 + lane * 4 + 2] = __floats2half2_rn(o1z, o1w);
    }
}

// ---------------- host launcher -----------------------------------------------
extern "C" void kernel_launch(void* const* d_in, const int* in_sizes, int n_in,
                              void* d_out, int out_size) {
    const float* x   = (const float*)d_in[0];
    const float* Wq  = (const float*)d_in[1];
    const float* Wk  = (const float*)d_in[2];
    const float* Wv  = (const float*)d_in[3];
    const float* Wo  = (const float*)d_in[4];
    const float* lq1 = (const float*)d_in[5];
    const float* lk1 = (const float*)d_in[6];
    const float* lq2 = (const float*)d_in[7];
    const float* lk2 = (const float*)d_in[8];
    const float* gnw = (const float*)d_in[9];
    const float* gnb = (const float*)d_in[10];
    const int*   pos = (const int*)d_in[11];
    float* out = (float*)d_out;

    __half *pQh, *pKh, *pVh, *pXh, *pWqh, *pWkh, *pWvh, *pWoh, *pOh;
    cudaGetSymbolAddress((void**)&pQh, g_Qh);
    cudaGetSymbolAddress((void**)&pKh, g_Kh);
    cudaGetSymbolAddress((void**)&pVh, g_Vh);
    cudaGetSymbolAddress((void**)&pXh, g_Xh);
    cudaGetSymbolAddress((void**)&pWqh, g_Wqh);
    cudaGetSymbolAddress((void**)&pWkh, g_Wkh);
    cudaGetSymbolAddress((void**)&pWvh, g_Wvh);
    cudaGetSymbolAddress((void**)&pWoh, g_Woh);
    cudaGetSymbolAddress((void**)&pOh, g_Oh);

    const int M = B_ * T_;   // 2048
    const int attn_smem = SMH_TOT * 2;  // 171008 B
    cudaFuncSetAttribute(attn_kernel, cudaFuncAttributeMaxDynamicSharedMemorySize, attn_smem);
    cudaFuncSetAttribute(gemm_qkv_h, cudaFuncAttributeMaxDynamicSharedMemorySize, GEMM_SMEM_BYTES);
    cudaFuncSetAttribute(gemm_out_h, cudaFuncAttributeMaxDynamicSharedMemorySize, GEMM_SMEM_BYTES);

    // lambda + rope table (one launch)
    prep_kernel<<<(T_ * 64 + 255) / 256, 256>>>(lq1, lk1, lq2, lk2, pos);

    {
        int total = S0_ + S1_ + S2_ + S3_ + S4_;
        f2h5_kernel<<<(total + 255) / 256, 256>>>(x, Wq, Wk, Wv, Wo,
                                                  pXh, pWqh, pWkh, pWvh, pWoh);
    }

    gemm_qkv_h<<<dim3(48, M / 128), 256, GEMM_SMEM_BYTES>>>(pXh, pWqh, pWkh, pWvh,
                                                            pQh, pKh, pVh);

    attn_kernel<<<dim3(T_ / 64, B_ * H_), 512, attn_smem>>>(pQh, pKh, pVh, pOh, gnw, gnb);

    gemm_out_h<<<dim3(D_ / 128, M / 128), 256, GEMM_SMEM_BYTES>>>(pOh, pWoh, out, D_, 4096);
}

// round 17
// speedup vs baseline: 1.0060x; 1.0060x over previous
#include <cuda_runtime.h>
#include <cuda_fp16.h>
#include <math.h>
#include <stdint.h>

#define B_  2
#define T_  1024
#define D_  2048
#define H_  16
#define KVH_ 4
#define DH_ 128
#define REP_ 4

#define LAMBDA_INIT_F   0.35550906759096927f
#define ONE_MINUS_LI_F  0.64449093240903073f
#define GN_EPS_F        1e-5f
#define SCALE_F         0.08838834764831845f  // 1/sqrt(128)
#define ROPE_C          (-13.287712379549449f / 64.0f)   // -log2(10000)/64

// fp16 GEMM pipeline: BK=32 (two k16 slabs), 4 stages, row stride 40 halves
#define BKH  32
#define LDH  40
#define GEMM_SMEM_BYTES (4 * 128 * LDH * 2 * 2)   // 81920 B

// ---------------- scratch ----------------------------------------------------
static __device__ __half g_Qh[(size_t)B_*T_*H_*2*DH_];
static __device__ __half g_Kh[(size_t)B_*T_*KVH_*2*DH_];
static __device__ __half g_Vh[(size_t)B_*T_*KVH_*2*DH_];
static __device__ __half g_Xh[(size_t)B_*T_*D_];
static __device__ __half g_Wqh[(size_t)2*H_*DH_*D_];
static __device__ __half g_Wkh[(size_t)2*KVH_*DH_*D_];
static __device__ __half g_Wvh[(size_t)2*KVH_*DH_*D_];
static __device__ __half g_Woh[(size_t)D_*2*H_*DH_];
static __device__ __half g_Oh[(size_t)B_*T_*H_*2*DH_];
static __device__ float2 g_rope[(size_t)T_ * 64];
static __device__ float  g_lambda;

// ---------------- helpers ----------------------------------------------------
__device__ __forceinline__ void mma_f16(float* c, const uint32_t* a, const uint32_t* b) {
    asm volatile(
        "mma.sync.aligned.m16n8k16.row.col.f32.f16.f16.f32 "
        "{%0,%1,%2,%3}, {%4,%5,%6,%7}, {%8,%9}, {%0,%1,%2,%3};"
        : "+f"(c[0]), "+f"(c[1]), "+f"(c[2]), "+f"(c[3])
        : "r"(a[0]), "r"(a[1]), "r"(a[2]), "r"(a[3]), "r"(b[0]), "r"(b[1]));
}
__device__ __forceinline__ void ldsm4(uint32_t* r, uint32_t a) {
    asm volatile("ldmatrix.sync.aligned.m8n8.x4.shared.b16 {%0,%1,%2,%3}, [%4];"
        : "=r"(r[0]), "=r"(r[1]), "=r"(r[2]), "=r"(r[3]) : "r"(a));
}
__device__ __forceinline__ void ldsm4t(uint32_t* r, uint32_t a) {
    asm volatile("ldmatrix.sync.aligned.m8n8.x4.trans.shared.b16 {%0,%1,%2,%3}, [%4];"
        : "=r"(r[0]), "=r"(r[1]), "=r"(r[2]), "=r"(r[3]) : "r"(a));
}
__device__ __forceinline__ void cp_async16(uint32_t smem_dst, const void* gsrc) {
    asm volatile("cp.async.cg.shared.global [%0], [%1], 16;" :: "r"(smem_dst), "l"(gsrc));
}
__device__ __forceinline__ void cp_commit() {
    asm volatile("cp.async.commit_group;" ::: "memory");
}
template <int N>
__device__ __forceinline__ void cp_wait() {
    asm volatile("cp.async.wait_group %0;" :: "n"(N) : "memory");
}
__device__ __forceinline__ uint32_t h2_bits(float a, float b) {
    __half2 t = __floats2half2_rn(a, b);
    return *(uint32_t*)&t;
}
__device__ __forceinline__ void bar_pair(int id) {
    asm volatile("bar.sync %0, 64;" :: "r"(id) : "memory");
}

// ---------------- fused fp32 -> fp16 convert for 5 tensors --------------------
#define S0_ 1048576
#define S1_ 2097152
#define S2_ 524288
#define S3_ 524288
#define S4_ 2097152
__global__ void f2h5_kernel(const float* __restrict__ x,  const float* __restrict__ Wq,
                            const float* __restrict__ Wk, const float* __restrict__ Wv,
                            const float* __restrict__ Wo,
                            __half* __restrict__ xh,  __half* __restrict__ Wqh,
                            __half* __restrict__ Wkh, __half* __restrict__ Wvh,
                            __half* __restrict__ Woh) {
    int i = blockIdx.x * blockDim.x + threadIdx.x;
    const float* s; __half* d; int off;
    if (i < S0_)                       { s = x;  d = xh;  off = i; }
    else if (i < S0_ + S1_)            { s = Wq; d = Wqh; off = i - S0_; }
    else if (i < S0_ + S1_ + S2_)      { s = Wk; d = Wkh; off = i - S0_ - S1_; }
    else if (i < S0_ + S1_ + S2_ + S3_){ s = Wv; d = Wvh; off = i - S0_ - S1_ - S2_; }
    else                               { s = Wo; d = Woh; off = i - S0_ - S1_ - S2_ - S3_; }
    float4 v = ((const float4*)s)[off];
    ((__half2*)d)[2 * off]     = __floats2half2_rn(v.x, v.y);
    ((__half2*)d)[2 * off + 1] = __floats2half2_rn(v.z, v.w);
}

// ---------------- prep: lambda scalar + RoPE cos/sin table --------------------
__global__ void prep_kernel(const float* __restrict__ lq1, const float* __restrict__ lk1,
                            const float* __restrict__ lq2, const float* __restrict__ lk2,
                            const int* __restrict__ pos) {
    int gid = blockIdx.x * blockDim.x + threadIdx.x;
    if (gid < T_ * 64) {
        int i = gid & 63;
        int t = gid >> 6;
        float inv = exp2f((float)i * ROPE_C);
        float ang = (float)pos[t] * inv;
        float s, c;
        sincosf(ang, &s, &c);
        g_rope[gid] = make_float2(c, s);
    }
    if (blockIdx.x == 0 && threadIdx.x < 32) {
        int lane = threadIdx.x;
        float d1 = 0.f, d2 = 0.f;
        #pragma unroll
        for (int i = 0; i < 4; i++) {
            int idx = lane * 4 + i;
            d1 += lq1[idx] * lk1[idx];
            d2 += lq2[idx] * lk2[idx];
        }
        #pragma unroll
        for (int o = 16; o; o >>= 1) {
            d1 += __shfl_xor_sync(0xffffffffu, d1, o);
            d2 += __shfl_xor_sync(0xffffffffu, d2, o);
        }
        if (lane == 0)
            g_lambda = expf(d1) - expf(d2) + LAMBDA_INIT_F;
    }
}

// ---------------- fp16 m16n8k16 GEMM body (BK=32, ldmatrix, 4-stage cp.async) -
template <int MODE>
__device__ __forceinline__ void gemm_body_h(
    const __half* __restrict__ Ablk, const __half* __restrict__ Bblk,
    void* __restrict__ Cblk, int K, int ldc, __half* smem,
    int rowbase, int colbase, float scale)
{
    const int tid  = threadIdx.x;
    const int warp = tid >> 5;
    const int lane = tid & 31;
    const int wm = (warp >> 2) * 64;
    const int wn = (warp & 3) * 32;
    const int lr = lane >> 2;
    const int lc = lane & 3;

    const uint32_t smb = (uint32_t)__cvta_generic_to_shared(smem);
    const uint32_t bofs = 4u * 128u * LDH * 2;

    const int l_row0 = tid >> 2;
    const int l_row1 = l_row0 + 64;
    const int l_c0   = (tid & 3) * 8;
    const __half* Ag0 = Ablk + (size_t)l_row0 * K + l_c0;
    const __half* Ag1 = Ablk + (size_t)l_row1 * K + l_c0;
    const __half* Bg0 = Bblk + (size_t)l_row0 * K + l_c0;
    const __half* Bg1 = Bblk + (size_t)l_row1 * K + l_c0;

    uint32_t a_dst0[4], a_dst1[4];
    #pragma unroll
    for (int s = 0; s < 4; s++) {
        a_dst0[s] = smb + (s * 128 * LDH + l_row0 * LDH + l_c0) * 2;
        a_dst1[s] = smb + (s * 128 * LDH + l_row1 * LDH + l_c0) * 2;
    }

    const int a_lr  = lane & 15;
    const int a_c8  = (lane >> 4) * 8;
    const int b_row = (lane & 7) + ((lane >> 4) << 3);
    const int b_k8  = ((lane >> 3) & 1) * 8;

    uint32_t a_lm[4], b_lm[4];
    #pragma unroll
    for (int s = 0; s < 4; s++) {
        a_lm[s] = smb + (s * 128 * LDH + (wm + a_lr) * LDH + a_c8) * 2;
        b_lm[s] = smb + bofs + (s * 128 * LDH + (wn + b_row) * LDH + b_k8) * 2;
    }

    float acc[4][4][4];
    #pragma unroll
    for (int mi = 0; mi < 4; mi++)
        #pragma unroll
        for (int ni = 0; ni < 4; ni++)
            #pragma unroll
            for (int r = 0; r < 4; r++)
                acc[mi][ni][r] = 0.f;

    const int nt = K / BKH;

    #pragma unroll
    for (int p = 0; p < 3; p++) {
        const size_t k0 = (size_t)p * BKH;
        cp_async16(a_dst0[p],        Ag0 + k0);
        cp_async16(a_dst1[p],        Ag1 + k0);
        cp_async16(a_dst0[p] + bofs, Bg0 + k0);
        cp_async16(a_dst1[p] + bofs, Bg1 + k0);
        cp_commit();
    }

    for (int t = 0; t < nt; t++) {
        cp_wait<2>();
        __syncthreads();
        const int s = t & 3;

        #pragma unroll
        for (int kk = 0; kk < 2; kk++) {
            uint32_t af[4][4], bf[4][2];
            #pragma unroll
            for (int mi = 0; mi < 4; mi++)
                ldsm4(af[mi], a_lm[s] + kk * 32 + mi * (16 * LDH * 2));
            {
                uint32_t bt[4];
                ldsm4(bt, b_lm[s] + kk * 32);
                bf[0][0] = bt[0]; bf[0][1] = bt[1]; bf[1][0] = bt[2]; bf[1][1] = bt[3];
                ldsm4(bt, b_lm[s] + kk * 32 + 16 * LDH * 2);
                bf[2][0] = bt[0]; bf[2][1] = bt[1]; bf[3][0] = bt[2]; bf[3][1] = bt[3];
            }
            #pragma unroll
            for (int mi = 0; mi < 4; mi++)
                #pragma unroll
                for (int ni = 0; ni < 4; ni++)
                    mma_f16(acc[mi][ni], af[mi], bf[ni]);
        }

        if (t + 3 < nt) {
            const int sn = (t + 3) & 3;
            const size_t k0 = (size_t)(t + 3) * BKH;
            cp_async16(a_dst0[sn],        Ag0 + k0);
            cp_async16(a_dst1[sn],        Ag1 + k0);
            cp_async16(a_dst0[sn] + bofs, Bg0 + k0);
            cp_async16(a_dst1[sn] + bofs, Bg1 + k0);
        }
        cp_commit();
    }

    #pragma unroll
    for (int mi = 0; mi < 4; mi++) {
        #pragma unroll
        for (int ni = 0; ni < 4; ni++) {
            int r0 = wm + mi * 16 + lr;
            int cc = wn + ni * 8 + 2 * lc;
            if (MODE == 2) {
                __half* Ch = (__half*)Cblk;
                int ip = ((colbase + cc) & 127) >> 1;
                int t0 = (rowbase + r0) & (T_ - 1);
                int t1 = (rowbase + r0 + 8) & (T_ - 1);
                float2 cs0 = g_rope[t0 * 64 + ip];
                float2 cs1 = g_rope[t1 * 64 + ip];
                float e0 = (acc[mi][ni][0] * cs0.x - acc[mi][ni][1] * cs0.y) * scale;
                float o0 = (acc[mi][ni][0] * cs0.y + acc[mi][ni][1] * cs0.x) * scale;
                float e1 = (acc[mi][ni][2] * cs1.x - acc[mi][ni][3] * cs1.y) * scale;
                float o1 = (acc[mi][ni][2] * cs1.y + acc[mi][ni][3] * cs1.x) * scale;
                *(__half2*)&Ch[(size_t)r0 * ldc + cc]       = __floats2half2_rn(e0, o0);
                *(__half2*)&Ch[(size_t)(r0 + 8) * ldc + cc] = __floats2half2_rn(e1, o1);
            } else if (MODE == 1) {
                __half* Ch = (__half*)Cblk;
                *(__half2*)&Ch[(size_t)r0 * ldc + cc] =
                    __floats2half2_rn(acc[mi][ni][0], acc[mi][ni][1]);
                *(__half2*)&Ch[(size_t)(r0 + 8) * ldc + cc] =
                    __floats2half2_rn(acc[mi][ni][2], acc[mi][ni][3]);
            } else {
                float* Cf = (float*)Cblk;
                *(float2*)&Cf[(size_t)r0 * ldc + cc] =
                    make_float2(acc[mi][ni][0], acc[mi][ni][1]);
                *(float2*)&Cf[(size_t)(r0 + 8) * ldc + cc] =
                    make_float2(acc[mi][ni][2], acc[mi][ni][3]);
            }
        }
    }
}

__global__ void __launch_bounds__(256, 2) gemm_qkv_h(const __half* __restrict__ x,
                                                     const __half* __restrict__ Wq,
                                                     const __half* __restrict__ Wk,
                                                     const __half* __restrict__ Wv,
                                                     __half* __restrict__ Qh,
                                                     __half* __restrict__ Kh,
                                                     __half* __restrict__ Vh) {
    extern __shared__ __half hsmem[];
    const int bx = blockIdx.x;
    const int bm = blockIdx.y * 128;
    if (bx < 32) {
        int bn = bx * 128;
        gemm_body_h<2>(x + (size_t)bm * D_, Wq + (size_t)bn * D_,
                       Qh + (size_t)bm * 4096 + bn, D_, 4096, hsmem,
                       bm, bn, SCALE_F);
    } else if (bx < 40) {
        int bn = (bx - 32) * 128;
        gemm_body_h<2>(x + (size_t)bm * D_, Wk + (size_t)bn * D_,
                       Kh + (size_t)bm * 1024 + bn, D_, 1024, hsmem,
                       bm, bn, 1.0f);
    } else {
        int bn = (bx - 40) * 128;
        gemm_body_h<1>(x + (size_t)bm * D_, Wv + (size_t)bn * D_,
                       Vh + (size_t)bm * 1024 + bn, D_, 1024, hsmem,
                       0, 0, 1.0f);
    }
}

__global__ void __launch_bounds__(256, 2) gemm_out_h(const __half* __restrict__ A,
                                                     const __half* __restrict__ W,
                                                     float* __restrict__ C,
                                                     int N, int K) {
    extern __shared__ __half hsmem[];
    const int bm = blockIdx.y * 128;
    const int bn = blockIdx.x * 128;
    gemm_body_h<0>(A + (size_t)bm * K, W + (size_t)bn * K,
                   C + (size_t)bm * N + bn, K, N, hsmem,
                   0, 0, 1.0f);
}

// ---------------- fp16 dual flash attention + GroupNorm -----------------------
// 64 q/CTA, 512 thr = 16 warps: br(2) x rg(4) x vh(2).
// vh=0 computes S+softmax ONCE per pair, shares P + corrections via smem;
// both warps run PV on their V half. Named barrier per (br,rg) pair.
// halves: stage s at s*34304: K1[64][136] | K2[64][136] | V[64][264]
// QS[64][264] at 68608; Psm 8 pairs x 2 bufs x 16x40 at 85504; cf at 95744.
#define SMH_STAGE 34304
#define SMH_K2O   8704
#define SMH_VO    17408
#define SMH_QS    68608
#define SMH_P     85504
#define SMH_CF    95744
#define SMH_TOT   96256      // halves -> 192512 B

__global__ void __launch_bounds__(512, 1) attn_kernel(const __half* __restrict__ Qh,
                                                      const __half* __restrict__ Kh,
                                                      const __half* __restrict__ Vh,
                                                      __half* __restrict__ Oh,
                                                      const float* __restrict__ gnw,
                                                      const float* __restrict__ gnb) {
    extern __shared__ __half hs[];
    __half (*QS)[264]  = (__half(*)[264])(hs + SMH_QS);
    float  (*Osm)[264] = (float(*)[264])hs;
    float* cfp = (float*)(hs + SMH_CF);

    const int tid  = threadIdx.x;
    const int warp = tid >> 5;
    const int lane = tid & 31;
    const int lr = lane >> 2;
    const int lc = lane & 3;
    const int br = warp >> 3;
    const int rg = (warp >> 1) & 3;
    const int vh = warp & 1;
    const int pair = warp >> 1;      // 0..7
    const int barid = 1 + pair;

    const int bh = blockIdx.y;
    const int b = bh / H_;
    const int h = bh % H_;
    const int kvh = h / REP_;
    const int q0 = (gridDim.x - 1 - blockIdx.x) * 64;

    const uint32_t hsb = (uint32_t)__cvta_generic_to_shared(hs);

    const int lm_r = (lane & 7) + ((lane >> 3) & 1) * 8;
    const int lm_c8 = (lane >> 4) * 8;

    const uint32_t q_addr0 = hsb + (SMH_QS + (rg * 16 + lm_r) * 264 + br * 128 + lm_c8) * 2;
    const int k_key = (lane >> 4) * 8 + (lane & 7);
    const int k_dim = ((lane >> 3) & 1) * 8;
    const uint32_t k_base = hsb + ((br ? SMH_K2O : 0) + k_key * 136 + k_dim) * 2;
    const int v_key = ((lane >> 3) & 1) * 8 + (lane & 7);
    const uint32_t v_base = hsb + (SMH_VO + v_key * 264 + vh * 128 + (lane >> 4) * 8) * 2;
    // P ldsm base per buffer (A-frag layout, 16x40 halves)
    const uint32_t p_lm_base = hsb + (SMH_P + pair * 2 * 640 + lm_r * 40 + lm_c8) * 2;

    // ---- stage Q ----
    #pragma unroll
    for (int r = 0; r < 4; r++) {
        int idx = tid + 512 * r;
        int qr = idx >> 5;
        int c8 = (idx & 31) * 8;
        uint4 v = *(const uint4*)&Qh[((size_t)(b * T_ + q0 + qr) * H_ + h) * 256 + c8];
        *(uint4*)&QS[qr][c8] = v;
    }

    float oacc[16][4];
    #pragma unroll
    for (int n = 0; n < 16; n++)
        #pragma unroll
        for (int r = 0; r < 4; r++)
            oacc[n][r] = 0.f;
    float m0 = -1e30f, m1 = -1e30f, l0 = 0.f, l1 = 0.f;

    const int row0 = q0 + rg * 16 + lr;
    const int row1 = row0 + 8;
    const int ntiles = q0 / 64 + 1;

    auto issue_tile = [&](int kt, int st) {
        const int k0 = kt * 64;
        const uint32_t sb = hsb + st * (SMH_STAGE * 2);
        #pragma unroll
        for (int r = 0; r < 4; r++) {
            int idx = tid + 512 * r;
            int key = idx >> 5;
            int c8 = idx & 31;
            size_t kb = ((size_t)(b * T_ + k0 + key) * KVH_ + kvh) * 256;
            uint32_t kd;
            if (c8 < 16) kd = sb + (key * 136 + c8 * 8) * 2;
            else         kd = sb + (SMH_K2O + key * 136 + (c8 - 16) * 8) * 2;
            cp_async16(kd, &Kh[kb + c8 * 8]);
            cp_async16(sb + (SMH_VO + key * 264 + c8 * 8) * 2, &Vh[kb + c8 * 8]);
        }
    };

    issue_tile(0, 0);
    cp_commit();

    for (int kt = 0; kt < ntiles; kt++) {
        const int st = kt & 1;

        cp_wait<0>();
        __syncthreads();
        if (kt + 1 < ntiles) {
            issue_tile(kt + 1, st ^ 1);
            cp_commit();
        }

        const uint32_t soff = st * (SMH_STAGE * 2);
        const bool lasttile = (kt == ntiles - 1);

        #pragma unroll
        for (int hk = 0; hk < 2; hk++) {
            const int k0 = kt * 64 + hk * 32;
            const int sub = kt * 2 + hk;
            const int pb = sub & 1;
            const uint32_t v_addr0 = v_base + soff + hk * (32 * 264 * 2);
            __half* Pp = hs + SMH_P + (pair * 2 + pb) * 640;
            float* cfb = cfp + (pair * 2 + pb) * 16;

            if (vh == 0) {
                const uint32_t k_addr0 = k_base + soff + hk * (32 * 136 * 2);
                float sf[4][4];
                #pragma unroll
                for (int n = 0; n < 4; n++)
                    #pragma unroll
                    for (int r = 0; r < 4; r++)
                        sf[n][r] = 0.f;
                #pragma unroll
                for (int ks = 0; ks < 8; ks++) {
                    uint32_t qa[4], kb0[4], kb1[4];
                    ldsm4(qa, q_addr0 + ks * 32);
                    ldsm4(kb0, k_addr0 + ks * 32);
                    ldsm4(kb1, k_addr0 + ks * 32 + 16 * 136 * 2);
                    mma_f16(sf[0], qa, kb0);
                    mma_f16(sf[1], qa, kb0 + 2);
                    mma_f16(sf[2], qa, kb1);
                    mma_f16(sf[3], qa, kb1 + 2);
                }

                if (lasttile) {
                    #pragma unroll
                    for (int n = 0; n < 4; n++) {
                        int key = k0 + n * 8 + 2 * lc;
                        if (key     > row0) sf[n][0] = -1e30f;
                        if (key + 1 > row0) sf[n][1] = -1e30f;
                        if (key     > row1) sf[n][2] = -1e30f;
                        if (key + 1 > row1) sf[n][3] = -1e30f;
                    }
                }

                float mx0 = -1e30f, mx1 = -1e30f;
                #pragma unroll
                for (int n = 0; n < 4; n++) {
                    mx0 = fmaxf(mx0, fmaxf(sf[n][0], sf[n][1]));
                    mx1 = fmaxf(mx1, fmaxf(sf[n][2], sf[n][3]));
                }
                mx0 = fmaxf(mx0, __shfl_xor_sync(0xffffffffu, mx0, 1));
                mx0 = fmaxf(mx0, __shfl_xor_sync(0xffffffffu, mx0, 2));
                mx1 = fmaxf(mx1, __shfl_xor_sync(0xffffffffu, mx1, 1));
                mx1 = fmaxf(mx1, __shfl_xor_sync(0xffffffffu, mx1, 2));

                float mn0 = fmaxf(m0, mx0), mn1 = fmaxf(m1, mx1);
                float c0 = __expf(m0 - mn0), c1 = __expf(m1 - mn1);
                m0 = mn0; m1 = mn1;

                float rs0 = 0.f, rs1 = 0.f;
                #pragma unroll
                for (int n = 0; n < 4; n++) {
                    sf[n][0] = __expf(sf[n][0] - mn0);
                    sf[n][1] = __expf(sf[n][1] - mn0);
                    sf[n][2] = __expf(sf[n][2] - mn1);
                    sf[n][3] = __expf(sf[n][3] - mn1);
                    rs0 += sf[n][0] + sf[n][1];
                    rs1 += sf[n][2] + sf[n][3];
                }
                rs0 += __shfl_xor_sync(0xffffffffu, rs0, 1);
                rs0 += __shfl_xor_sync(0xffffffffu, rs0, 2);
                rs1 += __shfl_xor_sync(0xffffffffu, rs1, 1);
                rs1 += __shfl_xor_sync(0xffffffffu, rs1, 2);
                l0 = l0 * c0 + rs0;
                l1 = l1 * c1 + rs1;

                // P -> smem (A-frag layout)
                #pragma unroll
                for (int n = 0; n < 4; n++) {
                    *(__half2*)&Pp[lr * 40 + n * 8 + 2 * lc] =
                        __floats2half2_rn(sf[n][0], sf[n][1]);
                    *(__half2*)&Pp[(lr + 8) * 40 + n * 8 + 2 * lc] =
                        __floats2half2_rn(sf[n][2], sf[n][3]);
                }
                if (lc == 0) {
                    cfb[lr] = c0;
                    cfb[8 + lr] = c1;
                }
            }

            bar_pair(barid);

            // both warps: read corrections, scale, PV
            float c0 = cfb[lr];
            float c1 = cfb[8 + lr];
            #pragma unroll
            for (int n = 0; n < 16; n++) {
                oacc[n][0] *= c0; oacc[n][1] *= c0;
                oacc[n][2] *= c1; oacc[n][3] *= c1;
            }

            const uint32_t p_addr0 = p_lm_base + pb * 1280;
            #pragma unroll
            for (int ks = 0; ks < 2; ks++) {
                uint32_t pa[4];
                ldsm4(pa, p_addr0 + ks * 32);
                #pragma unroll
                for (int np = 0; np < 8; np++) {
                    uint32_t vb4[4];
                    ldsm4t(vb4, v_addr0 + ks * (16 * 264 * 2) + np * 32);
                    mma_f16(oacc[np * 2],     pa, vb4);
                    mma_f16(oacc[np * 2 + 1], pa, vb4 + 2);
                }
            }
        }
    }

    // exchange l0/l1 to vh=1
    if (vh == 0 && lc == 0) {
        cfp[pair * 32 + lr] = l0;
        cfp[pair * 32 + 8 + lr] = l1;
    }
    bar_pair(barid);
    if (vh == 1) {
        l0 = cfp[pair * 32 + lr];
        l1 = cfp[pair * 32 + 8 + lr];
    }

    // ---- epilogue: combine branches, GroupNorm ----
    __syncthreads();
    const int orow0 = rg * 16 + lr;
    const int vb = vh * 128;
    if (br == 0) {
        float r0 = 1.f / l0, r1 = 1.f / l1;
        #pragma unroll
        for (int n = 0; n < 16; n++) {
            *(float2*)&Osm[orow0]    [vb + n * 8 + 2 * lc] =
                make_float2(oacc[n][0] * r0, oacc[n][1] * r0);
            *(float2*)&Osm[orow0 + 8][vb + n * 8 + 2 * lc] =
                make_float2(oacc[n][2] * r1, oacc[n][3] * r1);
        }
    }
    __syncthreads();
    if (br == 1) {
        const float lam = g_lambda;
        float r0 = lam / l0, r1 = lam / l1;
        #pragma unroll
        for (int n = 0; n < 16; n++) {
            float2 a0 = *(float2*)&Osm[orow0]    [vb + n * 8 + 2 * lc];
            float2 a1 = *(float2*)&Osm[orow0 + 8][vb + n * 8 + 2 * lc];
            a0.x -= oacc[n][0] * r0; a0.y -= oacc[n][1] * r0;
            a1.x -= oacc[n][2] * r1; a1.y -= oacc[n][3] * r1;
            *(float2*)&Osm[orow0]    [vb + n * 8 + 2 * lc] = a0;
            *(float2*)&Osm[orow0 + 8][vb + n * 8 + 2 * lc] = a1;
        }
    }
    __syncthreads();

    const float4 gw0 = *(const float4*)&gnw[h * 256 + lane * 4];
    const float4 gw1 = *(const float4*)&gnw[h * 256 + 128 + lane * 4];
    const float4 gb0 = *(const float4*)&gnb[h * 256 + lane * 4];
    const float4 gb1 = *(const float4*)&gnb[h * 256 + 128 + lane * 4];
    #pragma unroll
    for (int i = 0; i < 4; i++) {
        int r = warp * 4 + i;
        float4 v0 = *(float4*)&Osm[r][lane * 4];
        float4 v1 = *(float4*)&Osm[r][128 + lane * 4];
        float sum = v0.x + v0.y + v0.z + v0.w + v1.x + v1.y + v1.z + v1.w;
        float ss  = v0.x*v0.x + v0.y*v0.y + v0.z*v0.z + v0.w*v0.w
                  + v1.x*v1.x + v1.y*v1.y + v1.z*v1.z + v1.w*v1.w;
        #pragma unroll
        for (int o = 16; o; o >>= 1) {
            sum += __shfl_xor_sync(0xffffffffu, sum, o);
            ss  += __shfl_xor_sync(0xffffffffu, ss, o);
        }
        float mean = sum * (1.f / 256.f);
        float var = ss * (1.f / 256.f) - mean * mean;
        float rstd = rsqrtf(var + GN_EPS_F);
        float o0x = ((v0.x - mean) * rstd * gw0.x + gb0.x) * ONE_MINUS_LI_F;
        float o0y = ((v0.y - mean) * rstd * gw0.y + gb0.y) * ONE_MINUS_LI_F;
        float o0z = ((v0.z - mean) * rstd * gw0.z + gb0.z) * ONE_MINUS_LI_F;
        float o0w = ((v0.w - mean) * rstd * gw0.w + gb0.w) * ONE_MINUS_LI_F;
        float o1x = ((v1.x - mean) * rstd * gw1.x + gb1.x) * ONE_MINUS_LI_F;
        float o1y = ((v1.y - mean) * rstd * gw1.y + gb1.y) * ONE_MINUS_LI_F;
        float o1z = ((v1.z - mean) * rstd * gw1.z + gb1.z) * ONE_MINUS_LI_F;
        float o1w = ((v1.w - mean) * rstd * gw1.w + gb1.w) * ONE_MINUS_LI_F;
        size_t ob = (size_t)(b * T_ + q0 + r) * 4096 + h * 256;
        *(__half2*)&Oh[ob + lane * 4]           = __floats2half2_rn(o0x, o0y);
        *(__half2*)&Oh[ob + lane * 4 + 2]       = __floats2half2_rn(o0z, o0w);
        *(__half2*)&Oh[ob + 128 + lane * 4]     = __floats2half2_rn(o1x, o1y);
        *(__half2*)&Oh[ob + 128 + lane * 4 + 2] = __floats2half2_rn(o1z, o1w);
    }
}

// ---------------- host launcher -----------------------------------------------
extern "C" void kernel_launch(void* const* d_in, const int* in_sizes, int n_in,
                              void* d_out, int out_size) {
    const float* x   = (const float*)d_in[0];
    const float* Wq  = (const float*)d_in[1];
    const float* Wk  = (const float*)d_in[2];
    const float* Wv  = (const float*)d_in[3];
    const float* Wo  = (const float*)d_in[4];
    const float* lq1 = (const float*)d_in[5];
    const float* lk1 = (const float*)d_in[6];
    const float* lq2 = (const float*)d_in[7];
    const float* lk2 = (const float*)d_in[8];
    const float* gnw = (const float*)d_in[9];
    const float* gnb = (const float*)d_in[10];
    const int*   pos = (const int*)d_in[11];
    float* out = (float*)d_out;

    __half *pQh, *pKh, *pVh, *pXh, *pWqh, *pWkh, *pWvh, *pWoh, *pOh;
    cudaGetSymbolAddress((void**)&pQh, g_Qh);
    cudaGetSymbolAddress((void**)&pKh, g_Kh);
    cudaGetSymbolAddress((void**)&pVh, g_Vh);
    cudaGetSymbolAddress((void**)&pXh, g_Xh);
    cudaGetSymbolAddress((void**)&pWqh, g_Wqh);
    cudaGetSymbolAddress((void**)&pWkh, g_Wkh);
    cudaGetSymbolAddress((void**)&pWvh, g_Wvh);
    cudaGetSymbolAddress((void**)&pWoh, g_Woh);
    cudaGetSymbolAddress((void**)&pOh, g_Oh);

    const int M = B_ * T_;   // 2048
    const int attn_smem = SMH_TOT * 2;  // 192512 B
    cudaFuncSetAttribute(attn_kernel, cudaFuncAttributeMaxDynamicSharedMemorySize, attn_smem);
    cudaFuncSetAttribute(gemm_qkv_h, cudaFuncAttributeMaxDynamicSharedMemorySize, GEMM_SMEM_BYTES);
    cudaFuncSetAttribute(gemm_out_h, cudaFuncAttributeMaxDynamicSharedMemorySize, GEMM_SMEM_BYTES);

    prep_kernel<<<(T_ * 64 + 255) / 256, 256>>>(lq1, lk1, lq2, lk2, pos);

    {
        int total = S0_ + S1_ + S2_ + S3_ + S4_;
        f2h5_kernel<<<(total + 255) / 256, 256>>>(x, Wq, Wk, Wv, Wo,
                                                  pXh, pWqh, pWkh, pWvh, pWoh);
    }

    gemm_qkv_h<<<dim3(48, M / 128), 256, GEMM_SMEM_BYTES>>>(pXh, pWqh, pWkh, pWvh,
                                                            pQh, pKh, pVh);

    attn_kernel<<<dim3(T_ / 64, B_ * H_), 512, attn_smem>>>(pQh, pKh, pVh, pOh, gnw, gnb);

    gemm_out_h<<<dim3(D_ / 128, M / 128), 256, GEMM_SMEM_BYTES>>>(pOh, pWoh, out, D_, 4096);
}